// round 3
// baseline (speedup 1.0000x reference)
#include <cuda_runtime.h>
#include <math.h>

#define BB 64
#define SS 512
#define FF 128
#define UU 512
#define SIGDIM (FF + FF*FF)   /* 16512 */
#define NBF 8
#define TT (SS-1)             /* 511 */
#define BU (BB*UU)            /* 32768 */

/* ---------------- scratch (no allocations allowed) ---------------- */
__device__ float g_sig[BB*SIGDIM];     /* 4.2 MB: [s1(128) | s2(128x128)] per batch */
__device__ float g_z1[BU];
__device__ float g_zs[BU];
__device__ float g_h1[BU];
__device__ float g_h2[BU];
__device__ float g_g3[BU];
__device__ float g_g4[BU];
__device__ float g_attn[BU];
__device__ float g_Ab[BB*FF];
__device__ float g_As[BB*FF*NBF];
__device__ float g_cur[BU];
__device__ float g_comb[BB*2*UU];
__device__ float g_gates[4*BU];

/* ---------------- zero the atomic accumulators ---------------- */
__global__ void k_zero()
{
    int i = blockIdx.x * blockDim.x + threadIdx.x;
    int n = blockDim.x * gridDim.x;
    for (int j = i; j < BU; j += n) {
        g_z1[j] = 0.f; g_zs[j] = 0.f; g_h2[j] = 0.f;
        g_g3[j] = 0.f; g_g4[j] = 0.f; g_cur[j] = 0.f;
        g_gates[j] = 0.f; g_gates[BU + j] = 0.f;
        g_gates[2*BU + j] = 0.f; g_gates[3*BU + j] = 0.f;
    }
    for (int j = i; j < BB*FF*NBF; j += n) {
        g_As[j] = 0.f;
        if (j < BB*FF) g_Ab[j] = 0.f;
    }
}

/* ---------------- signature: s1 + s2 -----------------------------
   w[t,f] = tk[t]*x[b,t,f]
   s1[f]  = w[S-1,f] - w[0,f]
   P[t,f] = 0.5*(w[t,f]+w[t+1,f]) - w[0,f]   (closed-form cumsum)
   D[t,f] = w[t+1,f]-w[t,f]
   s2[i,j] = sum_t P[t,i]*D[t,j]
   grid: (4 tiles of 64x64, 64 batches), 256 threads                */
__global__ void k_sig(const float* __restrict__ X, const float* __restrict__ tk)
{
    int tile = blockIdx.x;           /* 0..3 */
    int b    = blockIdx.y;           /* 0..63 */
    int i0 = (tile >> 1) * 64;
    int j0 = (tile & 1) * 64;
    int tid = threadIdx.x;
    const float* Xb = X + (size_t)b * SS * FF;
    float tk0 = __ldg(&tk[0]);

    __shared__ __align__(16) float Psh[32*64];
    __shared__ __align__(16) float Dsh[32*64];

    int ty = tid >> 4, tx = tid & 15;
    float acc[4][4] = {};

    for (int t0 = 0; t0 < TT; t0 += 32) {
        int csize = TT - t0; if (csize > 32) csize = 32;
        __syncthreads();
        #pragma unroll
        for (int e = 0; e < 8; e++) {
            int lin = tid + e * 256;
            int k = lin >> 6, c = lin & 63;
            float pv = 0.f, dv = 0.f;
            if (k < csize) {
                int t = t0 + k;
                float tkt  = __ldg(&tk[t]);
                float tkt1 = __ldg(&tk[t+1]);
                int fi = i0 + c;
                float wt_i  = tkt  * __ldg(&Xb[(size_t)t*FF + fi]);
                float wt1_i = tkt1 * __ldg(&Xb[(size_t)(t+1)*FF + fi]);
                float w0_i  = tk0  * __ldg(&Xb[fi]);
                pv = 0.5f*(wt_i + wt1_i) - w0_i;
                int fj = j0 + c;
                dv = tkt1 * __ldg(&Xb[(size_t)(t+1)*FF + fj])
                   - tkt  * __ldg(&Xb[(size_t)t*FF + fj]);
            }
            Psh[k*64 + c] = pv;
            Dsh[k*64 + c] = dv;
        }
        __syncthreads();
        #pragma unroll
        for (int k = 0; k < 32; k++) {
            float4 p = *reinterpret_cast<const float4*>(&Psh[k*64 + ty*4]);
            float4 d = *reinterpret_cast<const float4*>(&Dsh[k*64 + tx*4]);
            float pa[4] = {p.x, p.y, p.z, p.w};
            float da[4] = {d.x, d.y, d.z, d.w};
            #pragma unroll
            for (int i = 0; i < 4; i++)
                #pragma unroll
                for (int j = 0; j < 4; j++)
                    acc[i][j] += pa[i] * da[j];
        }
    }

    float* dst = g_sig + (size_t)b*SIGDIM + FF;
    #pragma unroll
    for (int i = 0; i < 4; i++) {
        float4 v = make_float4(acc[i][0], acc[i][1], acc[i][2], acc[i][3]);
        *reinterpret_cast<float4*>(&dst[(size_t)(i0 + ty*4 + i)*FF + j0 + tx*4]) = v;
    }
    if (tile == 0 && tid < FF) {
        g_sig[(size_t)b*SIGDIM + tid] =
            __ldg(&tk[SS-1]) * Xb[(size_t)(SS-1)*FF + tid] - tk0 * Xb[tid];
    }
}

/* ---------------- generic M=64, N-tile=64 split-K GEMM, atomic out ----- */
__device__ __forceinline__ void gemm64_tile(
    const float* __restrict__ A, int lda, const float* __restrict__ abias,
    const float* __restrict__ Bw, int ldb, float* __restrict__ out, int ldo,
    int n0, int k0, int Kchunk)
{
    __shared__ __align__(16) float Ash[64*9];
    __shared__ __align__(16) float Bsh[8*64];
    int tid = threadIdx.x;
    int ty = tid >> 4, tx = tid & 15;
    int am = tid >> 2, ac = (tid & 3) * 2;
    int br = tid >> 5, bn = (tid & 31) * 2;
    float acc[4][4] = {};
    for (int kk = 0; kk < Kchunk; kk += 8) {
        int kg = k0 + kk;
        {
            float a0 = A[(size_t)am*lda + kg + ac];
            float a1 = A[(size_t)am*lda + kg + ac + 1];
            if (abias) { a0 += abias[kg + ac]; a1 += abias[kg + ac + 1]; }
            Ash[am*9 + ac]     = a0;
            Ash[am*9 + ac + 1] = a1;
        }
        {
            const float* bp = Bw + (size_t)(kg + br)*ldb + n0 + bn;
            Bsh[br*64 + bn]     = bp[0];
            Bsh[br*64 + bn + 1] = bp[1];
        }
        __syncthreads();
        #pragma unroll
        for (int c = 0; c < 8; c++) {
            float4 bv = *reinterpret_cast<const float4*>(&Bsh[c*64 + tx*4]);
            float av[4];
            #pragma unroll
            for (int i = 0; i < 4; i++) av[i] = Ash[(ty*4 + i)*9 + c];
            #pragma unroll
            for (int i = 0; i < 4; i++) {
                acc[i][0] += av[i]*bv.x;
                acc[i][1] += av[i]*bv.y;
                acc[i][2] += av[i]*bv.z;
                acc[i][3] += av[i]*bv.w;
            }
        }
        __syncthreads();
    }
    #pragma unroll
    for (int i = 0; i < 4; i++)
        #pragma unroll
        for (int j = 0; j < 4; j++)
            atomicAdd(&out[(size_t)(ty*4 + i)*ldo + n0 + tx*4 + j], acc[i][j]);
}

/* B-transposed variant: B[k][n] = Bw[(n0+n)*ldb + k] (spline_w is (U,F*NB)) */
__device__ __forceinline__ void gemm64_tile_bt(
    const float* __restrict__ A, int lda,
    const float* __restrict__ Bw, int ldb, float* __restrict__ out, int ldo,
    int n0, int k0, int Kchunk)
{
    __shared__ __align__(16) float Ash[64*9];
    __shared__ __align__(16) float Bsh[8*64];
    int tid = threadIdx.x;
    int ty = tid >> 4, tx = tid & 15;
    int am = tid >> 2, ac = (tid & 3) * 2;
    float acc[4][4] = {};
    for (int kk = 0; kk < Kchunk; kk += 8) {
        int kg = k0 + kk;
        {
            Ash[am*9 + ac]     = A[(size_t)am*lda + kg + ac];
            Ash[am*9 + ac + 1] = A[(size_t)am*lda + kg + ac + 1];
        }
        {
            int n = tid >> 2, c0 = (tid & 3) * 2;
            const float* bp = Bw + (size_t)(n0 + n)*ldb + kg + c0;
            Bsh[c0*64 + n]       = bp[0];
            Bsh[(c0 + 1)*64 + n] = bp[1];
        }
        __syncthreads();
        #pragma unroll
        for (int c = 0; c < 8; c++) {
            float4 bv = *reinterpret_cast<const float4*>(&Bsh[c*64 + tx*4]);
            float av[4];
            #pragma unroll
            for (int i = 0; i < 4; i++) av[i] = Ash[(ty*4 + i)*9 + c];
            #pragma unroll
            for (int i = 0; i < 4; i++) {
                acc[i][0] += av[i]*bv.x;
                acc[i][1] += av[i]*bv.y;
                acc[i][2] += av[i]*bv.z;
                acc[i][3] += av[i]*bv.w;
            }
        }
        __syncthreads();
    }
    #pragma unroll
    for (int i = 0; i < 4; i++)
        #pragma unroll
        for (int j = 0; j < 4; j++)
            atomicAdd(&out[(size_t)(ty*4 + i)*ldo + n0 + tx*4 + j], acc[i][j]);
}

/* z1 = sig@w1, zs = sig@ws   grid (8 ntiles, 16 ksplit, 2 which) */
__global__ void k_siggemm(const float* __restrict__ w1, const float* __restrict__ ws)
{
    const float* w = blockIdx.z ? ws : w1;
    float* o       = blockIdx.z ? g_zs : g_z1;
    gemm64_tile(g_sig, SIGDIM, nullptr, w, UU, o, UU,
                blockIdx.x * 64, blockIdx.y * 1032, 1032);
}

/* h1 = elu(z1 + b1) */
__global__ void k_h1(const float* __restrict__ b1)
{
    int i = blockIdx.x * blockDim.x + threadIdx.x;
    float v = g_z1[i] + b1[i & (UU - 1)];
    g_h1[i] = v > 0.f ? v : expm1f(v);
}

/* h2 = h1@w2 (bias folded later)   grid (8, 8) */
__global__ void k_h2(const float* __restrict__ w2)
{
    gemm64_tile(g_h1, UU, nullptr, w2, UU, g_h2, UU,
                blockIdx.x * 64, blockIdx.y * 64, 64);
}

/* g3 = (h2+b2)@w3, g4 = (h2+b2)@w4   grid (8, 8, 2) */
__global__ void k_g34(const float* __restrict__ b2,
                      const float* __restrict__ w3, const float* __restrict__ w4)
{
    const float* w = blockIdx.z ? w4 : w3;
    float* o       = blockIdx.z ? g_g4 : g_g3;
    gemm64_tile(g_h2, UU, b2, w, UU, o, UU,
                blockIdx.x * 64, blockIdx.y * 64, 64);
}

/* glu + skip + layernorm + softmax -> attn   grid 64, 512 threads */
__global__ void k_lnsm(const float* __restrict__ b3, const float* __restrict__ b4,
                       const float* __restrict__ bs, const float* __restrict__ gamma,
                       const float* __restrict__ beta)
{
    __shared__ float red[512];
    int b = blockIdx.x, u = threadIdx.x;
    int idx = b * UU + u;
    float g3v = g_g3[idx] + b3[u];
    float g4v = g_g4[idx] + b4[u];
    float y = g_zs[idx] + bs[u] + (1.f / (1.f + expf(-g3v))) * g4v;

    red[u] = y; __syncthreads();
    for (int s = 256; s > 0; s >>= 1) { if (u < s) red[u] += red[u + s]; __syncthreads(); }
    float mu = red[0] * (1.f / UU); __syncthreads();

    float d = y - mu;
    red[u] = d * d; __syncthreads();
    for (int s = 256; s > 0; s >>= 1) { if (u < s) red[u] += red[u + s]; __syncthreads(); }
    float var = red[0] * (1.f / UU); __syncthreads();

    float yn = d * rsqrtf(var + 1e-3f) * gamma[u] + beta[u];

    red[u] = yn; __syncthreads();
    for (int s = 256; s > 0; s >>= 1) { if (u < s) red[u] = fmaxf(red[u], red[u + s]); __syncthreads(); }
    float mx = red[0]; __syncthreads();

    float e = expf(yn - mx);
    red[u] = e; __syncthreads();
    for (int s = 256; s > 0; s >>= 1) { if (u < s) red[u] += red[u + s]; __syncthreads(); }
    g_attn[idx] = e / red[0];
}

/* cubic b-spline bases on uniform extended grid, matches Cox-de Boor recursion */
__device__ __forceinline__ void bspline8(float x, float* bs)
{
    const float h = 0.4f;
    float b0[11];
    #pragma unroll
    for (int i = 0; i < 11; i++) {
        float gi  = -1.0f + h * (float)(i - 3);
        float gi1 = -1.0f + h * (float)(i - 2);
        b0[i] = (x >= gi && x < gi1) ? 1.0f : 0.0f;
    }
    float b1[10];
    #pragma unroll
    for (int i = 0; i < 10; i++) {
        float gi  = -1.0f + h * (float)(i - 3);
        float gip = -1.0f + h * (float)(i - 1);   /* g[i+2] */
        b1[i] = ((x - gi) * b0[i] + (gip - x) * b0[i + 1]) * (1.0f / h);
    }
    float b2[9];
    #pragma unroll
    for (int i = 0; i < 9; i++) {
        float gi  = -1.0f + h * (float)(i - 3);
        float gip = -1.0f + h * (float)(i);       /* g[i+3] */
        b2[i] = ((x - gi) * b1[i] + (gip - x) * b1[i + 1]) * (1.0f / (2.0f * h));
    }
    #pragma unroll
    for (int i = 0; i < 8; i++) {
        float gi  = -1.0f + h * (float)(i - 3);
        float gip = -1.0f + h * (float)(i + 1);   /* g[i+4] */
        bs[i] = ((x - gi) * b2[i] + (gip - x) * b2[i + 1]) * (1.0f / (3.0f * h));
    }
}

/* attn-weighted reductions over s:
   Ab[b,f]   = sum_s attn[b,s]*silu(w[b,s,f])
   As[b,f,k] = sum_s attn[b,s]*bspline(w[b,s,f])[k]
   grid (64 batches, 8 s-chunks), 128 threads (f)                       */
__global__ void k_reduce(const float* __restrict__ X, const float* __restrict__ tk)
{
    int b  = blockIdx.x;
    int s0 = blockIdx.y * 64;
    int f  = threadIdx.x;
    const float* Xb = X + (size_t)b * SS * FF;
    float accb = 0.f;
    float accs[NBF] = {};
    for (int ss = 0; ss < 64; ss++) {
        int s = s0 + ss;
        float a  = __ldg(&g_attn[b * UU + s]);
        float xv = __ldg(&tk[s]) * Xb[(size_t)s * FF + f];
        float sg = 1.f / (1.f + expf(-xv));
        accb += a * (xv * sg);
        float bsv[NBF];
        bspline8(xv, bsv);
        #pragma unroll
        for (int k = 0; k < NBF; k++) accs[k] += a * bsv[k];
    }
    atomicAdd(&g_Ab[b * FF + f], accb);
    #pragma unroll
    for (int k = 0; k < NBF; k++)
        atomicAdd(&g_As[(size_t)(b * FF + f) * NBF + k], accs[k]);
}

/* current*S = Ab@base_w + As . spline_w   grid (8 ntiles, 5 parts) */
__global__ void k_cur(const float* __restrict__ base_w, const float* __restrict__ spline_w)
{
    int n0 = blockIdx.x * 64;
    int part = blockIdx.y;
    if (part == 0)
        gemm64_tile(g_Ab, FF, nullptr, base_w, UU, g_cur, UU, n0, 0, FF);
    else
        gemm64_tile_bt(g_As, FF * NBF, spline_w, FF * NBF, g_cur, UU,
                       n0, (part - 1) * 256, 256);
}

/* combined = [current/S, h_prev] */
__global__ void k_comb(const float* __restrict__ h_prev)
{
    int i = blockIdx.x * blockDim.x + threadIdx.x;   /* B*1024 */
    int m = i >> 10, k = i & 1023;
    g_comb[i] = (k < UU) ? g_cur[m * UU + k] * (1.0f / SS)
                         : h_prev[m * UU + (k - UU)];
}

/* 4 gate GEMMs   grid (8 ntiles, 4 gates, 4 ksplit) */
__global__ void k_lstm(const float* __restrict__ wf, const float* __restrict__ wi,
                       const float* __restrict__ wc, const float* __restrict__ wo)
{
    const float* w = (blockIdx.y == 0) ? wf : (blockIdx.y == 1) ? wi
                   : (blockIdx.y == 2) ? wc : wo;
    float* o = g_gates + (size_t)blockIdx.y * BU;
    gemm64_tile(g_comb, 2 * UU, nullptr, w, UU, o, UU,
                blockIdx.x * 64, blockIdx.z * 256, 256);
}

/* gate nonlinearities + state update */
__global__ void k_fin(const float* __restrict__ c_prev,
                      const float* __restrict__ bf, const float* __restrict__ bi,
                      const float* __restrict__ bc, const float* __restrict__ bo,
                      float* __restrict__ out, int out_size)
{
    int i = blockIdx.x * blockDim.x + threadIdx.x;   /* BU */
    int u = i & (UU - 1);
    float fg = 1.f / (1.f + expf(-(g_gates[i]           + bf[u])));
    float ig = 1.f / (1.f + expf(-(g_gates[BU + i]      + bi[u])));
    float cd = tanhf(          g_gates[2 * BU + i] + bc[u]);
    float og = 1.f / (1.f + expf(-(g_gates[3 * BU + i]  + bo[u])));
    float c = fg * c_prev[i] + ig * cd;
    float h = og * tanhf(c);
    out[i] = h;
    if (out_size >= 2 * BU) out[BU + i] = c;
}

/* ------------------------------------------------------------------ */
extern "C" void kernel_launch(void* const* d_in, const int* in_sizes, int n_in,
                              void* d_out, int out_size)
{
    const float* X       = (const float*)d_in[0];   /* inputs (B,S,F)   */
    const float* h_prev  = (const float*)d_in[1];
    const float* c_prev  = (const float*)d_in[2];
    const float* tk      = (const float*)d_in[3];   /* time_kernel (S,1)*/
    const float* base_w  = (const float*)d_in[4];   /* (F,U)            */
    const float* spl_w   = (const float*)d_in[5];   /* (U,F,NB)         */
    const float* w1      = (const float*)d_in[6];
    const float* b1      = (const float*)d_in[7];
    const float* w2      = (const float*)d_in[8];
    const float* b2      = (const float*)d_in[9];
    const float* w3      = (const float*)d_in[10];
    const float* b3      = (const float*)d_in[11];
    const float* w4      = (const float*)d_in[12];
    const float* b4      = (const float*)d_in[13];
    const float* ws      = (const float*)d_in[14];
    const float* bs      = (const float*)d_in[15];
    const float* gamma   = (const float*)d_in[16];
    const float* beta    = (const float*)d_in[17];
    const float* wf      = (const float*)d_in[18];
    const float* bf      = (const float*)d_in[19];
    const float* wi      = (const float*)d_in[20];
    const float* bi      = (const float*)d_in[21];
    const float* wc      = (const float*)d_in[22];
    const float* bc      = (const float*)d_in[23];
    const float* wo      = (const float*)d_in[24];
    const float* bo      = (const float*)d_in[25];
    float* out = (float*)d_out;

    k_zero   <<<256, 256>>>();
    k_sig    <<<dim3(4, BB), 256>>>(X, tk);
    k_siggemm<<<dim3(8, 16, 2), 256>>>(w1, ws);
    k_h1     <<<BU / 256, 256>>>(b1);
    k_h2     <<<dim3(8, 8), 256>>>(w2);
    k_g34    <<<dim3(8, 8, 2), 256>>>(b2, w3, w4);
    k_lnsm   <<<BB, 512>>>(b3, b4, bs, gamma, beta);
    k_reduce <<<dim3(BB, 8), 128>>>(X, tk);
    k_cur    <<<dim3(8, 5), 256>>>(base_w, spl_w);
    k_comb   <<<(BB * 2 * UU) / 256, 256>>>(h_prev);
    k_lstm   <<<dim3(8, 4, 4), 256>>>(wf, wi, wc, wo);
    k_fin    <<<BU / 256, 256>>>(c_prev, bf, bi, bc, bo, out, out_size);
}

// round 5
// speedup vs baseline: 1.0079x; 1.0079x over previous
#include <cuda_runtime.h>
#include <math.h>

#define BB 64
#define SS 512
#define FF 128
#define UU 512
#define SIGDIM (FF + FF*FF)   /* 16512 */
#define NBF 8
#define TT (SS-1)             /* 511 */
#define BU (BB*UU)            /* 32768 */
#define KSTEP 16

typedef unsigned long long ull;

/* ---------------- packed f32x2 helpers ---------------- */
__device__ __forceinline__ ull fma2(ull a, ull b, ull c)
{
    ull d;
    asm("fma.rn.f32x2 %0, %1, %2, %3;" : "=l"(d) : "l"(a), "l"(b), "l"(c));
    return d;
}
__device__ __forceinline__ float2 unpack2(ull v)
{
    float2 f;
    asm("mov.b64 {%0,%1}, %2;" : "=f"(f.x), "=f"(f.y) : "l"(v));
    return f;
}

/* ---------------- scratch (no allocations allowed) ---------------- */
__device__ float g_sig[BB*SIGDIM];
__device__ float g_z1[BU];
__device__ float g_zs[BU];
__device__ float g_h2[BU];
__device__ float g_g3[BU];
__device__ float g_g4[BU];
__device__ float g_attn[BU];
__device__ float g_Ab[BB*FF];
__device__ float g_As[BB*FF*NBF];
__device__ float g_cur[BU];
__device__ float g_gates[4*BU];

/* ---------------- zero the atomic accumulators ---------------- */
__global__ void k_zero()
{
    int i = blockIdx.x * blockDim.x + threadIdx.x;
    int n = blockDim.x * gridDim.x;
    for (int j = i; j < BU; j += n) {
        g_z1[j] = 0.f; g_zs[j] = 0.f; g_h2[j] = 0.f;
        g_g3[j] = 0.f; g_g4[j] = 0.f; g_cur[j] = 0.f;
        g_gates[j] = 0.f; g_gates[BU + j] = 0.f;
        g_gates[2*BU + j] = 0.f; g_gates[3*BU + j] = 0.f;
    }
    for (int j = i; j < BB*FF*NBF; j += n) {
        g_As[j] = 0.f;
        if (j < BB*FF) g_Ab[j] = 0.f;
    }
}

/* ---------------- signature: s1 + s2 ------------------------------
   P[t,f] = 0.5*(w[t,f]+w[t+1,f]) - w[0,f]   (closed-form cumsum)
   D[t,f] = w[t+1,f]-w[t,f];  s2[i,j] = sum_t P[t,i]*D[t,j]
   f32x2 inner: P pairs over i (LDS.64), D duplicated {d,d} pairs.    */
__global__ void k_sig(const float* __restrict__ X, const float* __restrict__ tk)
{
    int tile = blockIdx.x;           /* 0..3 */
    int b    = blockIdx.y;           /* 0..63 */
    int i0 = (tile >> 1) * 64;
    int j0 = (tile & 1) * 64;
    int tid = threadIdx.x;
    const float* Xb = X + (size_t)b * SS * FF;
    float tk0 = __ldg(&tk[0]);

    __shared__ __align__(16) float PshT[32*66];
    __shared__ __align__(16) float Dsh2[32*132];
    __shared__ float w0sh[64];

    if (tid < 64) w0sh[tid] = tk0 * __ldg(&Xb[i0 + tid]);

    int ty = tid >> 4, tx = tid & 15;
    ull acc[2][4] = {{0ull,0ull,0ull,0ull},{0ull,0ull,0ull,0ull}};

    for (int t0 = 0; t0 < TT; t0 += 32) {
        __syncthreads();
        #pragma unroll
        for (int e = 0; e < 8; e++) {
            int lin = tid + e * 256;
            int k = lin >> 6, c = lin & 63;
            int t = t0 + k;
            float pv = 0.f, dv = 0.f;
            if (t < TT) {
                float tkt  = __ldg(&tk[t]);
                float tkt1 = __ldg(&tk[t+1]);
                float xi   = __ldg(&Xb[(size_t)t*FF + i0 + c]);
                float xi1  = __ldg(&Xb[(size_t)(t+1)*FF + i0 + c]);
                pv = 0.5f*(tkt*xi + tkt1*xi1) - w0sh[c];
                float xj   = __ldg(&Xb[(size_t)t*FF + j0 + c]);
                float xj1  = __ldg(&Xb[(size_t)(t+1)*FF + j0 + c]);
                dv = tkt1*xj1 - tkt*xj;
            }
            PshT[k*66 + c] = pv;
            Dsh2[k*132 + 2*c]     = dv;
            Dsh2[k*132 + 2*c + 1] = dv;
        }
        __syncthreads();
        #pragma unroll
        for (int t = 0; t < 32; t++) {
            ull a0 = *reinterpret_cast<const ull*>(&PshT[t*66 + ty*4]);
            ull a1 = *reinterpret_cast<const ull*>(&PshT[t*66 + ty*4 + 2]);
            const float* base = &Dsh2[t*132 + 2*tx];
            ull b0 = *reinterpret_cast<const ull*>(base);
            ull b1 = *reinterpret_cast<const ull*>(base + 32);
            ull b2 = *reinterpret_cast<const ull*>(base + 64);
            ull b3 = *reinterpret_cast<const ull*>(base + 96);
            acc[0][0] = fma2(a0,b0,acc[0][0]); acc[0][1] = fma2(a0,b1,acc[0][1]);
            acc[0][2] = fma2(a0,b2,acc[0][2]); acc[0][3] = fma2(a0,b3,acc[0][3]);
            acc[1][0] = fma2(a1,b0,acc[1][0]); acc[1][1] = fma2(a1,b1,acc[1][1]);
            acc[1][2] = fma2(a1,b2,acc[1][2]); acc[1][3] = fma2(a1,b3,acc[1][3]);
        }
    }

    float* dst = g_sig + (size_t)b*SIGDIM + FF;
    #pragma unroll
    for (int ip = 0; ip < 2; ip++)
        #pragma unroll
        for (int q = 0; q < 4; q++) {
            float2 v = unpack2(acc[ip][q]);
            int mi = i0 + ty*4 + 2*ip;
            dst[(size_t)mi*FF + j0 + tx + 16*q]     = v.x;
            dst[(size_t)(mi+1)*FF + j0 + tx + 16*q] = v.y;
        }
    if (tile == 0 && tid < FF) {
        g_sig[(size_t)b*SIGDIM + tid] =
            __ldg(&tk[SS-1]) * Xb[(size_t)(SS-1)*FF + tid] - tk0 * Xb[tid];
    }
}

/* ---------------- M=64, N-tile=64 split-K f32x2 GEMM, atomic out -------
   AMODE: 0 plain, 1 elu(A+aux), 2 A+aux(bias), 3 concat [A*(1/S) | aux]
   BTRANS: 0 B row-major [K,N]; 1 B row-major [N,K] (use B^T)            */
template<int AMODE, int BTRANS>
__device__ __forceinline__ void gemm64(
    const float* __restrict__ A, int lda, const float* __restrict__ aux,
    const float* __restrict__ Bw, int ldb, float* __restrict__ out, int ldo,
    int n0, int k0, int Kchunk)
{
    __shared__ __align__(16) float AshT[KSTEP*66];
    __shared__ __align__(16) float Bsh2[KSTEP*132];
    int tid = threadIdx.x;
    int ty = tid >> 4, tx = tid & 15;
    int am = tid >> 2, ak = (tid & 3) * 4;
    ull acc[2][4] = {{0ull,0ull,0ull,0ull},{0ull,0ull,0ull,0ull}};

    for (int kk = 0; kk < Kchunk; kk += KSTEP) {
        int kg = k0 + kk;
        __syncthreads();
        /* stage A (transposed in smem) */
        {
            float4 av;
            if (AMODE == 3) {
                int k = kg + ak;
                if (k < UU) {
                    av = *reinterpret_cast<const float4*>(&A[(size_t)am*UU + k]);
                    av.x *= (1.f/SS); av.y *= (1.f/SS); av.z *= (1.f/SS); av.w *= (1.f/SS);
                } else {
                    av = *reinterpret_cast<const float4*>(&aux[(size_t)am*UU + k - UU]);
                }
            } else {
                av = *reinterpret_cast<const float4*>(&A[(size_t)am*lda + kg + ak]);
                if (AMODE >= 1) {
                    float4 bv = *reinterpret_cast<const float4*>(&aux[kg + ak]);
                    av.x += bv.x; av.y += bv.y; av.z += bv.z; av.w += bv.w;
                    if (AMODE == 1) {
                        av.x = av.x > 0.f ? av.x : expm1f(av.x);
                        av.y = av.y > 0.f ? av.y : expm1f(av.y);
                        av.z = av.z > 0.f ? av.z : expm1f(av.z);
                        av.w = av.w > 0.f ? av.w : expm1f(av.w);
                    }
                }
            }
            AshT[(ak+0)*66 + am] = av.x;
            AshT[(ak+1)*66 + am] = av.y;
            AshT[(ak+2)*66 + am] = av.z;
            AshT[(ak+3)*66 + am] = av.w;
        }
        /* stage B duplicated {b,b} */
        if (!BTRANS) {
            int br = tid >> 4;
            int bn = (tid & 15) * 4;
            float4 bv = *reinterpret_cast<const float4*>(&Bw[(size_t)(kg + br)*ldb + n0 + bn]);
            float* p = &Bsh2[br*132 + 2*bn];
            p[0]=bv.x; p[1]=bv.x; p[2]=bv.y; p[3]=bv.y;
            p[4]=bv.z; p[5]=bv.z; p[6]=bv.w; p[7]=bv.w;
        } else {
            int n  = tid >> 2;
            int k4 = (tid & 3) * 4;
            float4 bv = *reinterpret_cast<const float4*>(&Bw[(size_t)(n0 + n)*ldb + kg + k4]);
            Bsh2[(k4+0)*132 + 2*n] = bv.x; Bsh2[(k4+0)*132 + 2*n + 1] = bv.x;
            Bsh2[(k4+1)*132 + 2*n] = bv.y; Bsh2[(k4+1)*132 + 2*n + 1] = bv.y;
            Bsh2[(k4+2)*132 + 2*n] = bv.z; Bsh2[(k4+2)*132 + 2*n + 1] = bv.z;
            Bsh2[(k4+3)*132 + 2*n] = bv.w; Bsh2[(k4+3)*132 + 2*n + 1] = bv.w;
        }
        __syncthreads();
        #pragma unroll
        for (int c = 0; c < KSTEP; c++) {
            ull a0 = *reinterpret_cast<const ull*>(&AshT[c*66 + ty*4]);
            ull a1 = *reinterpret_cast<const ull*>(&AshT[c*66 + ty*4 + 2]);
            const float* base = &Bsh2[c*132 + 2*tx];
            ull b0 = *reinterpret_cast<const ull*>(base);
            ull b1 = *reinterpret_cast<const ull*>(base + 32);
            ull b2 = *reinterpret_cast<const ull*>(base + 64);
            ull b3 = *reinterpret_cast<const ull*>(base + 96);
            acc[0][0] = fma2(a0,b0,acc[0][0]); acc[0][1] = fma2(a0,b1,acc[0][1]);
            acc[0][2] = fma2(a0,b2,acc[0][2]); acc[0][3] = fma2(a0,b3,acc[0][3]);
            acc[1][0] = fma2(a1,b0,acc[1][0]); acc[1][1] = fma2(a1,b1,acc[1][1]);
            acc[1][2] = fma2(a1,b2,acc[1][2]); acc[1][3] = fma2(a1,b3,acc[1][3]);
        }
    }
    #pragma unroll
    for (int ip = 0; ip < 2; ip++)
        #pragma unroll
        for (int q = 0; q < 4; q++) {
            float2 v = unpack2(acc[ip][q]);
            int m = ty*4 + 2*ip;
            atomicAdd(&out[(size_t)m*ldo + n0 + tx + 16*q],     v.x);
            atomicAdd(&out[(size_t)(m+1)*ldo + n0 + tx + 16*q], v.y);
        }
}

/* z1 = sig@w1, zs = sig@ws   grid (8 ntiles, 24 ksplit, 2) */
__global__ void k_siggemm(const float* __restrict__ w1, const float* __restrict__ ws)
{
    const float* w = blockIdx.z ? ws : w1;
    float* o       = blockIdx.z ? g_zs : g_z1;
    gemm64<0,0>(g_sig, SIGDIM, nullptr, w, UU, o, UU,
                blockIdx.x * 64, blockIdx.y * 688, 688);
}

/* h2 = elu(z1+b1)@w2   grid (8, 8) */
__global__ void k_h2(const float* __restrict__ b1, const float* __restrict__ w2)
{
    gemm64<1,0>(g_z1, UU, b1, w2, UU, g_h2, UU,
                blockIdx.x * 64, blockIdx.y * 64, 64);
}

/* g3 = (h2+b2)@w3, g4 = (h2+b2)@w4   grid (8, 8, 2) */
__global__ void k_g34(const float* __restrict__ b2,
                      const float* __restrict__ w3, const float* __restrict__ w4)
{
    const float* w = blockIdx.z ? w4 : w3;
    float* o       = blockIdx.z ? g_g4 : g_g3;
    gemm64<2,0>(g_h2, UU, b2, w, UU, o, UU,
                blockIdx.x * 64, blockIdx.y * 64, 64);
}

/* glu + skip + layernorm + softmax -> attn   grid 64, 512 threads */
__global__ void k_lnsm(const float* __restrict__ b3, const float* __restrict__ b4,
                       const float* __restrict__ bs, const float* __restrict__ gamma,
                       const float* __restrict__ beta)
{
    __shared__ float sm[32];
    __shared__ float bc0, bc1;
    int b = blockIdx.x, u = threadIdx.x;
    int w = u >> 5, l = u & 31;
    int idx = b * UU + u;
    float g3v = g_g3[idx] + b3[u];
    float g4v = g_g4[idx] + b4[u];
    float y = g_zs[idx] + bs[u] + g4v / (1.f + __expf(-g3v));

    float s = y, q = y * y;
    #pragma unroll
    for (int o = 16; o; o >>= 1) {
        s += __shfl_xor_sync(0xffffffffu, s, o);
        q += __shfl_xor_sync(0xffffffffu, q, o);
    }
    if (l == 0) { sm[w] = s; sm[16 + w] = q; }
    __syncthreads();
    if (u < 32) {
        float v = sm[u];
        #pragma unroll
        for (int o = 8; o; o >>= 1) v += __shfl_xor_sync(0xffffffffu, v, o);
        if (u == 0)  bc0 = v;
        if (u == 16) bc1 = v;
    }
    __syncthreads();
    float mu  = bc0 * (1.f / UU);
    float var = bc1 * (1.f / UU) - mu * mu;
    float yn = (y - mu) * rsqrtf(var + 1e-3f) * gamma[u] + beta[u];

    float mx = yn;
    #pragma unroll
    for (int o = 16; o; o >>= 1) mx = fmaxf(mx, __shfl_xor_sync(0xffffffffu, mx, o));
    if (l == 0) sm[w] = mx;
    __syncthreads();
    if (w == 0) {
        float v = (l < 16) ? sm[l] : -3e38f;
        #pragma unroll
        for (int o = 8; o; o >>= 1) v = fmaxf(v, __shfl_xor_sync(0xffffffffu, v, o));
        if (l == 0) bc0 = v;
    }
    __syncthreads();
    float e = __expf(yn - bc0);
    float es = e;
    #pragma unroll
    for (int o = 16; o; o >>= 1) es += __shfl_xor_sync(0xffffffffu, es, o);
    if (l == 0) sm[w] = es;
    __syncthreads();
    if (w == 0) {
        float v = (l < 16) ? sm[l] : 0.f;
        #pragma unroll
        for (int o = 8; o; o >>= 1) v += __shfl_xor_sync(0xffffffffu, v, o);
        if (l == 0) bc1 = v;
    }
    __syncthreads();
    g_attn[idx] = e / bc1;
}

/* attn-weighted reductions; closed-form uniform cubic B-spline:
   x in interval m = floor((x+2.2)/0.4), u = frac; nonzero bases m-3..m:
   w(m)=u^3/6, w(m-1)=(1+3u+3u^2-3u^3)/6, w(m-2)=(4-6u^2+3u^3)/6, w(m-3)=(1-u)^3/6 */
__global__ void k_reduce(const float* __restrict__ X, const float* __restrict__ tk)
{
    int b  = blockIdx.x;
    int s0 = blockIdx.y * 64;
    int f  = threadIdx.x;
    const float* Xb = X + (size_t)b * SS * FF;
    float accb = 0.f;
    float accs[NBF] = {};
    for (int ss = 0; ss < 64; ss++) {
        int s = s0 + ss;
        float a  = __ldg(&g_attn[b * UU + s]);
        float xv = __ldg(&tk[s]) * __ldg(&Xb[(size_t)s * FF + f]);
        float sg = 1.f / (1.f + __expf(-xv));
        accb += a * (xv * sg);
        float xs = (xv + 2.2f) * 2.5f;
        float mf = floorf(xs);
        int m = (int)mf;
        float u  = xs - mf;
        float um = 1.f - u;
        float wd0 = u*u*u * (1.f/6.f);
        float wd1 = 0.66666667f + um*um*(0.5f*um - 1.f);
        float wd2 = 0.66666667f + u*u*(0.5f*u - 1.f);
        float wd3 = um*um*um * (1.f/6.f);
        #pragma unroll
        for (int k = 0; k < NBF; k++) {
            int d = m - k;
            float wv = (d == 0) ? wd0 : (d == 1) ? wd1 : (d == 2) ? wd2
                     : (d == 3) ? wd3 : 0.f;
            accs[k] += a * wv;
        }
    }
    atomicAdd(&g_Ab[b * FF + f], accb);
    #pragma unroll
    for (int k = 0; k < NBF; k++)
        atomicAdd(&g_As[(size_t)(b * FF + f) * NBF + k], accs[k]);
}

/* current*S = Ab@base_w + As . spline_w   grid (8 ntiles, 5 parts) */
__global__ void k_cur(const float* __restrict__ base_w, const float* __restrict__ spline_w)
{
    int n0 = blockIdx.x * 64;
    int part = blockIdx.y;
    if (part == 0)
        gemm64<0,0>(g_Ab, FF, nullptr, base_w, UU, g_cur, UU, n0, 0, FF);
    else
        gemm64<0,1>(g_As, FF * NBF, nullptr, spline_w, FF * NBF, g_cur, UU,
                    n0, (part - 1) * 256, 256);
}

/* 4 gate GEMMs, A = [cur/S | h_prev] built in A-load   grid (8, 4, 4) */
__global__ void k_lstm(const float* __restrict__ h_prev,
                       const float* __restrict__ wf, const float* __restrict__ wi,
                       const float* __restrict__ wc, const float* __restrict__ wo)
{
    const float* w = (blockIdx.y == 0) ? wf : (blockIdx.y == 1) ? wi
                   : (blockIdx.y == 2) ? wc : wo;
    float* o = g_gates + (size_t)blockIdx.y * BU;
    gemm64<3,0>(g_cur, UU, h_prev, w, UU, o, UU,
                blockIdx.x * 64, blockIdx.z * 256, 256);
}

/* gate nonlinearities + state update */
__global__ void k_fin(const float* __restrict__ c_prev,
                      const float* __restrict__ bf, const float* __restrict__ bi,
                      const float* __restrict__ bc, const float* __restrict__ bo,
                      float* __restrict__ out, int out_size)
{
    int i = blockIdx.x * blockDim.x + threadIdx.x;
    int u = i & (UU - 1);
    float fg = 1.f / (1.f + __expf(-(g_gates[i]          + bf[u])));
    float ig = 1.f / (1.f + __expf(-(g_gates[BU + i]     + bi[u])));
    float cd = tanhf(              g_gates[2 * BU + i]   + bc[u]);
    float og = 1.f / (1.f + __expf(-(g_gates[3 * BU + i] + bo[u])));
    float c = fg * c_prev[i] + ig * cd;
    float h = og * tanhf(c);
    out[i] = h;
    if (out_size >= 2 * BU) out[BU + i] = c;
}

/* ------------------------------------------------------------------ */
extern "C" void kernel_launch(void* const* d_in, const int* in_sizes, int n_in,
                              void* d_out, int out_size)
{
    const float* X       = (const float*)d_in[0];
    const float* h_prev  = (const float*)d_in[1];
    const float* c_prev  = (const float*)d_in[2];
    const float* tk      = (const float*)d_in[3];
    const float* base_w  = (const float*)d_in[4];
    const float* spl_w   = (const float*)d_in[5];
    const float* w1      = (const float*)d_in[6];
    const float* b1      = (const float*)d_in[7];
    const float* w2      = (const float*)d_in[8];
    const float* b2      = (const float*)d_in[9];
    const float* w3      = (const float*)d_in[10];
    const float* b3      = (const float*)d_in[11];
    const float* w4      = (const float*)d_in[12];
    const float* b4      = (const float*)d_in[13];
    const float* ws      = (const float*)d_in[14];
    const float* bs      = (const float*)d_in[15];
    const float* gamma   = (const float*)d_in[16];
    const float* beta    = (const float*)d_in[17];
    const float* wf      = (const float*)d_in[18];
    const float* bf      = (const float*)d_in[19];
    const float* wi      = (const float*)d_in[20];
    const float* bi      = (const float*)d_in[21];
    const float* wc      = (const float*)d_in[22];
    const float* bc      = (const float*)d_in[23];
    const float* wo      = (const float*)d_in[24];
    const float* bo      = (const float*)d_in[25];
    float* out = (float*)d_out;

    k_zero   <<<256, 256>>>();
    k_sig    <<<dim3(4, BB), 256>>>(X, tk);
    k_siggemm<<<dim3(8, 24, 2), 256>>>(w1, ws);
    k_h2     <<<dim3(8, 8), 256>>>(b1, w2);
    k_g34    <<<dim3(8, 8, 2), 256>>>(b2, w3, w4);
    k_lnsm   <<<BB, 512>>>(b3, b4, bs, gamma, beta);
    k_reduce <<<dim3(BB, 8), 128>>>(X, tk);
    k_cur    <<<dim3(8, 5), 256>>>(base_w, spl_w);
    k_lstm   <<<dim3(8, 4, 4), 256>>>(h_prev, wf, wi, wc, wo);
    k_fin    <<<BU / 256, 256>>>(c_prev, bf, bi, bc, bo, out, out_size);
}

// round 6
// speedup vs baseline: 1.1755x; 1.1663x over previous
#include <cuda_runtime.h>
#include <math.h>

#define BB 64
#define SS 512
#define FF 128
#define UU 512
#define SIGDIM (FF + FF*FF)   /* 16512 */
#define NBF 8
#define TT (SS-1)             /* 511 */
#define BU (BB*UU)            /* 32768 */
#define KSTEP 16

typedef unsigned long long ull;

/* ---------------- packed f32x2 helpers ---------------- */
__device__ __forceinline__ ull fma2(ull a, ull b, ull c)
{
    ull d;
    asm("fma.rn.f32x2 %0, %1, %2, %3;" : "=l"(d) : "l"(a), "l"(b), "l"(c));
    return d;
}
__device__ __forceinline__ float2 unpack2(ull v)
{
    float2 f;
    asm("mov.b64 {%0,%1}, %2;" : "=f"(f.x), "=f"(f.y) : "l"(v));
    return f;
}
__device__ __forceinline__ ull pack2(float x, float y)
{
    ull r;
    asm("mov.b64 %0, {%1,%2};" : "=l"(r) : "f"(x), "f"(y));
    return r;
}

/* ---------------- scratch (no allocations allowed) ---------------- */
__device__ float g_sig[BB*SIGDIM];
__device__ float g_z1[BU];
__device__ float g_zs[BU];
__device__ float g_h2[BU];
__device__ float g_g3[BU];
__device__ float g_g4[BU];
__device__ float g_attn[BU];
__device__ float g_Ab[BB*FF];
__device__ float g_As[BB*FF*NBF];
__device__ float g_cur[BU];
__device__ float g_gates[4*BU];

/* ---------------- zero the atomic accumulators ---------------- */
__global__ void k_zero()
{
    int i = blockIdx.x * blockDim.x + threadIdx.x;
    int n = blockDim.x * gridDim.x;
    for (int j = i; j < BU; j += n) {
        g_z1[j] = 0.f; g_zs[j] = 0.f; g_h2[j] = 0.f;
        g_g3[j] = 0.f; g_g4[j] = 0.f; g_cur[j] = 0.f;
        g_gates[j] = 0.f; g_gates[BU + j] = 0.f;
        g_gates[2*BU + j] = 0.f; g_gates[3*BU + j] = 0.f;
    }
    for (int j = i; j < BB*FF*NBF; j += n) {
        g_As[j] = 0.f;
        if (j < BB*FF) g_Ab[j] = 0.f;
    }
}

/* =================================================================
   Warp-broadcast FFMA2 GEMM core.
   CTA: 256 threads = 8 warps.  Tile: M=64 x N=128.
   warp w owns n in [16w,16w+16); lane l owns m in {2l,2l+1}.
   A staged duplicated ({a,a} pairs) -> one LDS.128 per lane (ulonglong2).
   B staged natural -> 4x LDS.128 warp-broadcast + mov.b64 packs.
   Per warp-k: 8 LDS wavefronts vs 16 FMA2 -> all pipes balance at peak.
   AMODE: 0 plain, 1 elu(A+aux), 2 A+aux, 3 concat [A*(1/S) | aux]
   BTRANS: 0 B is [K,N] row-major; 1 B is [N,K] row-major (use B^T)
   ================================================================= */
template<int AMODE, int BTRANS>
__device__ __forceinline__ void gemmW(
    const float* __restrict__ A, int lda, const float* __restrict__ aux,
    const float* __restrict__ Bw, int ldb, float* __restrict__ out, int ldo,
    int n0, int k0, int Kchunk)
{
    __shared__ __align__(16) float Adup[KSTEP][132];
    __shared__ __align__(16) float Bsh[KSTEP][132];
    int tid = threadIdx.x;
    int l = tid & 31;
    int nw = (tid >> 5) * 16;
    ull acc[2][8] = {{0,0,0,0,0,0,0,0},{0,0,0,0,0,0,0,0}};

    for (int kk = 0; kk < Kchunk; kk += KSTEP) {
        int kg = k0 + kk;
        __syncthreads();
        /* ---- stage A duplicated: thread m = tid>>2, k4 = (tid&3)*4 ---- */
        {
            int m = tid >> 2, k4 = (tid & 3) * 4;
            float4 av;
            if (AMODE == 3) {
                int k = kg + k4;
                if (k < UU) {
                    av = *reinterpret_cast<const float4*>(&A[(size_t)m*UU + k]);
                    av.x *= (1.f/SS); av.y *= (1.f/SS);
                    av.z *= (1.f/SS); av.w *= (1.f/SS);
                } else {
                    av = *reinterpret_cast<const float4*>(&aux[(size_t)m*UU + k - UU]);
                }
            } else {
                av = *reinterpret_cast<const float4*>(&A[(size_t)m*lda + kg + k4]);
                if (AMODE >= 1) {
                    float4 bv = *reinterpret_cast<const float4*>(&aux[kg + k4]);
                    av.x += bv.x; av.y += bv.y; av.z += bv.z; av.w += bv.w;
                    if (AMODE == 1) {
                        av.x = av.x > 0.f ? av.x : expm1f(av.x);
                        av.y = av.y > 0.f ? av.y : expm1f(av.y);
                        av.z = av.z > 0.f ? av.z : expm1f(av.z);
                        av.w = av.w > 0.f ? av.w : expm1f(av.w);
                    }
                }
            }
            *reinterpret_cast<float2*>(&Adup[k4+0][2*m]) = make_float2(av.x, av.x);
            *reinterpret_cast<float2*>(&Adup[k4+1][2*m]) = make_float2(av.y, av.y);
            *reinterpret_cast<float2*>(&Adup[k4+2][2*m]) = make_float2(av.z, av.z);
            *reinterpret_cast<float2*>(&Adup[k4+3][2*m]) = make_float2(av.w, av.w);
        }
        /* ---- stage B natural ---- */
        if (!BTRANS) {
            int k = tid >> 4, n8 = (tid & 15) * 8;
            const float* bp = &Bw[(size_t)(kg + k)*ldb + n0 + n8];
            float4 b0 = *reinterpret_cast<const float4*>(bp);
            float4 b1 = *reinterpret_cast<const float4*>(bp + 4);
            *reinterpret_cast<float4*>(&Bsh[k][n8])     = b0;
            *reinterpret_cast<float4*>(&Bsh[k][n8 + 4]) = b1;
        } else {
            int n = tid >> 1, kq = (tid & 1) * 8;
            const float* bp = &Bw[(size_t)(n0 + n)*ldb + kg + kq];
            float4 b0 = *reinterpret_cast<const float4*>(bp);
            float4 b1 = *reinterpret_cast<const float4*>(bp + 4);
            Bsh[kq+0][n] = b0.x; Bsh[kq+1][n] = b0.y;
            Bsh[kq+2][n] = b0.z; Bsh[kq+3][n] = b0.w;
            Bsh[kq+4][n] = b1.x; Bsh[kq+5][n] = b1.y;
            Bsh[kq+6][n] = b1.z; Bsh[kq+7][n] = b1.w;
        }
        __syncthreads();
        /* ---- inner ---- */
        #pragma unroll
        for (int c = 0; c < KSTEP; c++) {
            ulonglong2 av = *reinterpret_cast<const ulonglong2*>(&Adup[c][4*l]);
            float4 f0 = *reinterpret_cast<const float4*>(&Bsh[c][nw]);
            float4 f1 = *reinterpret_cast<const float4*>(&Bsh[c][nw + 4]);
            float4 f2 = *reinterpret_cast<const float4*>(&Bsh[c][nw + 8]);
            float4 f3 = *reinterpret_cast<const float4*>(&Bsh[c][nw + 12]);
            ull b[8];
            b[0] = pack2(f0.x, f0.y); b[1] = pack2(f0.z, f0.w);
            b[2] = pack2(f1.x, f1.y); b[3] = pack2(f1.z, f1.w);
            b[4] = pack2(f2.x, f2.y); b[5] = pack2(f2.z, f2.w);
            b[6] = pack2(f3.x, f3.y); b[7] = pack2(f3.z, f3.w);
            #pragma unroll
            for (int p = 0; p < 8; p++) {
                acc[0][p] = fma2(av.x, b[p], acc[0][p]);
                acc[1][p] = fma2(av.y, b[p], acc[1][p]);
            }
        }
    }
    /* ---- epilogue: atomics (split-K) ---- */
    #pragma unroll
    for (int p = 0; p < 8; p++) {
        float2 v0 = unpack2(acc[0][p]);
        float2 v1 = unpack2(acc[1][p]);
        int col = n0 + nw + 2*p;
        atomicAdd(&out[(size_t)(2*l)  *ldo + col],     v0.x);
        atomicAdd(&out[(size_t)(2*l)  *ldo + col + 1], v0.y);
        atomicAdd(&out[(size_t)(2*l+1)*ldo + col],     v1.x);
        atomicAdd(&out[(size_t)(2*l+1)*ldo + col + 1], v1.y);
    }
}

/* ---------------- signature: s1 + s2 ------------------------------
   P[t,i] = 0.5*(w[t,i]+w[t+1,i]) - w[0,i]; D[t,j] = w[t+1,j]-w[t,j]
   s2[i,j] = sum_t P[t,i]*D[t,j].  Same warp layout: P dup, D pairs.
   grid (2 m-tiles, 64 batches), 256 threads. Direct stores (no split-K). */
__global__ void k_sig(const float* __restrict__ X, const float* __restrict__ tk)
{
    int i0 = blockIdx.x * 64;
    int b  = blockIdx.y;
    int tid = threadIdx.x;
    int l = tid & 31;
    int nw = (tid >> 5) * 16;
    const float* Xb = X + (size_t)b * SS * FF;
    float tk0 = __ldg(&tk[0]);

    __shared__ __align__(16) float Pdup[KSTEP][132];
    __shared__ __align__(16) float Dsh[KSTEP][132];
    __shared__ float w0sh[64];

    if (tid < 64) w0sh[tid] = tk0 * __ldg(&Xb[i0 + tid]);

    ull acc[2][8] = {{0,0,0,0,0,0,0,0},{0,0,0,0,0,0,0,0}};

    for (int t0 = 0; t0 < TT; t0 += KSTEP) {
        __syncthreads();
        int tt = tid >> 4;
        int t  = t0 + tt;
        bool valid = t < TT;
        float tkt  = 0.f, tkt1 = 0.f;
        if (valid) { tkt = __ldg(&tk[t]); tkt1 = __ldg(&tk[t+1]); }
        /* P staging: quad of i */
        {
            int i4 = (tid & 15) * 4;
            float4 pv = make_float4(0.f, 0.f, 0.f, 0.f);
            if (valid) {
                float4 xi  = *reinterpret_cast<const float4*>(&Xb[(size_t)t*FF + i0 + i4]);
                float4 xi1 = *reinterpret_cast<const float4*>(&Xb[(size_t)(t+1)*FF + i0 + i4]);
                pv.x = 0.5f*(tkt*xi.x + tkt1*xi1.x) - w0sh[i4+0];
                pv.y = 0.5f*(tkt*xi.y + tkt1*xi1.y) - w0sh[i4+1];
                pv.z = 0.5f*(tkt*xi.z + tkt1*xi1.z) - w0sh[i4+2];
                pv.w = 0.5f*(tkt*xi.w + tkt1*xi1.w) - w0sh[i4+3];
            }
            *reinterpret_cast<float2*>(&Pdup[tt][2*(i4+0)]) = make_float2(pv.x, pv.x);
            *reinterpret_cast<float2*>(&Pdup[tt][2*(i4+1)]) = make_float2(pv.y, pv.y);
            *reinterpret_cast<float2*>(&Pdup[tt][2*(i4+2)]) = make_float2(pv.z, pv.z);
            *reinterpret_cast<float2*>(&Pdup[tt][2*(i4+3)]) = make_float2(pv.w, pv.w);
        }
        /* D staging: 8 j per thread */
        {
            int j8 = (tid & 15) * 8;
            float4 d0 = make_float4(0.f,0.f,0.f,0.f);
            float4 d1 = make_float4(0.f,0.f,0.f,0.f);
            if (valid) {
                float4 x0 = *reinterpret_cast<const float4*>(&Xb[(size_t)t*FF + j8]);
                float4 x1 = *reinterpret_cast<const float4*>(&Xb[(size_t)t*FF + j8 + 4]);
                float4 y0 = *reinterpret_cast<const float4*>(&Xb[(size_t)(t+1)*FF + j8]);
                float4 y1 = *reinterpret_cast<const float4*>(&Xb[(size_t)(t+1)*FF + j8 + 4]);
                d0.x = tkt1*y0.x - tkt*x0.x; d0.y = tkt1*y0.y - tkt*x0.y;
                d0.z = tkt1*y0.z - tkt*x0.z; d0.w = tkt1*y0.w - tkt*x0.w;
                d1.x = tkt1*y1.x - tkt*x1.x; d1.y = tkt1*y1.y - tkt*x1.y;
                d1.z = tkt1*y1.z - tkt*x1.z; d1.w = tkt1*y1.w - tkt*x1.w;
            }
            *reinterpret_cast<float4*>(&Dsh[tt][j8])     = d0;
            *reinterpret_cast<float4*>(&Dsh[tt][j8 + 4]) = d1;
        }
        __syncthreads();
        #pragma unroll
        for (int c = 0; c < KSTEP; c++) {
            ulonglong2 av = *reinterpret_cast<const ulonglong2*>(&Pdup[c][4*l]);
            float4 f0 = *reinterpret_cast<const float4*>(&Dsh[c][nw]);
            float4 f1 = *reinterpret_cast<const float4*>(&Dsh[c][nw + 4]);
            float4 f2 = *reinterpret_cast<const float4*>(&Dsh[c][nw + 8]);
            float4 f3 = *reinterpret_cast<const float4*>(&Dsh[c][nw + 12]);
            ull b[8];
            b[0] = pack2(f0.x, f0.y); b[1] = pack2(f0.z, f0.w);
            b[2] = pack2(f1.x, f1.y); b[3] = pack2(f1.z, f1.w);
            b[4] = pack2(f2.x, f2.y); b[5] = pack2(f2.z, f2.w);
            b[6] = pack2(f3.x, f3.y); b[7] = pack2(f3.z, f3.w);
            #pragma unroll
            for (int p = 0; p < 8; p++) {
                acc[0][p] = fma2(av.x, b[p], acc[0][p]);
                acc[1][p] = fma2(av.y, b[p], acc[1][p]);
            }
        }
    }

    float* dst = g_sig + (size_t)b*SIGDIM + FF;
    #pragma unroll
    for (int p = 0; p < 8; p++) {
        float2 v0 = unpack2(acc[0][p]);
        float2 v1 = unpack2(acc[1][p]);
        int col = nw + 2*p;
        *reinterpret_cast<float2*>(&dst[(size_t)(i0 + 2*l)    *FF + col]) = v0;
        *reinterpret_cast<float2*>(&dst[(size_t)(i0 + 2*l + 1)*FF + col]) = v1;
    }
    if (blockIdx.x == 0 && tid < FF) {
        g_sig[(size_t)b*SIGDIM + tid] =
            __ldg(&tk[SS-1]) * Xb[(size_t)(SS-1)*FF + tid] - tk0 * Xb[tid];
    }
}

/* z1 = sig@w1, zs = sig@ws   grid (4 ntiles, 43 ksplit, 2) Kchunk 384 */
__global__ void k_siggemm(const float* __restrict__ w1, const float* __restrict__ ws)
{
    const float* w = blockIdx.z ? ws : w1;
    float* o       = blockIdx.z ? g_zs : g_z1;
    gemmW<0,0>(g_sig, SIGDIM, nullptr, w, UU, o, UU,
               blockIdx.x * 128, blockIdx.y * 384, 384);
}

/* h2 = elu(z1+b1)@w2   grid (4, 16) Kchunk 32 */
__global__ void k_h2(const float* __restrict__ b1, const float* __restrict__ w2)
{
    gemmW<1,0>(g_z1, UU, b1, w2, UU, g_h2, UU,
               blockIdx.x * 128, blockIdx.y * 32, 32);
}

/* g3 = (h2+b2)@w3, g4 = (h2+b2)@w4   grid (4, 8, 2) Kchunk 64 */
__global__ void k_g34(const float* __restrict__ b2,
                      const float* __restrict__ w3, const float* __restrict__ w4)
{
    const float* w = blockIdx.z ? w4 : w3;
    float* o       = blockIdx.z ? g_g4 : g_g3;
    gemmW<2,0>(g_h2, UU, b2, w, UU, o, UU,
               blockIdx.x * 128, blockIdx.y * 64, 64);
}

/* glu + skip + layernorm + softmax -> attn   grid 64, 512 threads */
__global__ void k_lnsm(const float* __restrict__ b3, const float* __restrict__ b4,
                       const float* __restrict__ bs, const float* __restrict__ gamma,
                       const float* __restrict__ beta)
{
    __shared__ float sm[32];
    __shared__ float bc0, bc1;
    int b = blockIdx.x, u = threadIdx.x;
    int w = u >> 5, l = u & 31;
    int idx = b * UU + u;
    float g3v = g_g3[idx] + b3[u];
    float g4v = g_g4[idx] + b4[u];
    float y = g_zs[idx] + bs[u] + g4v / (1.f + __expf(-g3v));

    float s = y, q = y * y;
    #pragma unroll
    for (int o = 16; o; o >>= 1) {
        s += __shfl_xor_sync(0xffffffffu, s, o);
        q += __shfl_xor_sync(0xffffffffu, q, o);
    }
    if (l == 0) { sm[w] = s; sm[16 + w] = q; }
    __syncthreads();
    if (u < 32) {
        float v = sm[u];
        #pragma unroll
        for (int o = 8; o; o >>= 1) v += __shfl_xor_sync(0xffffffffu, v, o);
        if (u == 0)  bc0 = v;
        if (u == 16) bc1 = v;
    }
    __syncthreads();
    float mu  = bc0 * (1.f / UU);
    float var = bc1 * (1.f / UU) - mu * mu;
    float yn = (y - mu) * rsqrtf(var + 1e-3f) * gamma[u] + beta[u];

    float mx = yn;
    #pragma unroll
    for (int o = 16; o; o >>= 1) mx = fmaxf(mx, __shfl_xor_sync(0xffffffffu, mx, o));
    if (l == 0) sm[w] = mx;
    __syncthreads();
    if (w == 0) {
        float v = (l < 16) ? sm[l] : -3e38f;
        #pragma unroll
        for (int o = 8; o; o >>= 1) v = fmaxf(v, __shfl_xor_sync(0xffffffffu, v, o));
        if (l == 0) bc0 = v;
    }
    __syncthreads();
    float e = __expf(yn - bc0);
    float es = e;
    #pragma unroll
    for (int o = 16; o; o >>= 1) es += __shfl_xor_sync(0xffffffffu, es, o);
    if (l == 0) sm[w] = es;
    __syncthreads();
    if (w == 0) {
        float v = (l < 16) ? sm[l] : 0.f;
        #pragma unroll
        for (int o = 8; o; o >>= 1) v += __shfl_xor_sync(0xffffffffu, v, o);
        if (l == 0) bc1 = v;
    }
    __syncthreads();
    g_attn[idx] = e / bc1;
}

/* attn-weighted reductions; closed-form uniform cubic B-spline */
__global__ void k_reduce(const float* __restrict__ X, const float* __restrict__ tk)
{
    int b  = blockIdx.x;
    int s0 = blockIdx.y * 64;
    int f  = threadIdx.x;
    const float* Xb = X + (size_t)b * SS * FF;
    float accb = 0.f;
    float accs[NBF] = {};
    for (int ss = 0; ss < 64; ss++) {
        int s = s0 + ss;
        float a  = __ldg(&g_attn[b * UU + s]);
        float xv = __ldg(&tk[s]) * __ldg(&Xb[(size_t)s * FF + f]);
        float sg = 1.f / (1.f + __expf(-xv));
        accb += a * (xv * sg);
        float xs = (xv + 2.2f) * 2.5f;
        float mf = floorf(xs);
        int m = (int)mf;
        float u  = xs - mf;
        float um = 1.f - u;
        float wd0 = u*u*u * (1.f/6.f);
        float wd1 = 0.66666667f + um*um*(0.5f*um - 1.f);
        float wd2 = 0.66666667f + u*u*(0.5f*u - 1.f);
        float wd3 = um*um*um * (1.f/6.f);
        #pragma unroll
        for (int k = 0; k < NBF; k++) {
            int d = m - k;
            float wv = (d == 0) ? wd0 : (d == 1) ? wd1 : (d == 2) ? wd2
                     : (d == 3) ? wd3 : 0.f;
            accs[k] += a * wv;
        }
    }
    atomicAdd(&g_Ab[b * FF + f], accb);
    #pragma unroll
    for (int k = 0; k < NBF; k++)
        atomicAdd(&g_As[(size_t)(b * FF + f) * NBF + k], accs[k]);
}

/* current*S = Ab@base_w + As . spline_w   grid (4 ntiles, 9 parts) */
__global__ void k_cur(const float* __restrict__ base_w, const float* __restrict__ spline_w)
{
    int n0 = blockIdx.x * 128;
    int part = blockIdx.y;
    if (part == 0)
        gemmW<0,0>(g_Ab, FF, nullptr, base_w, UU, g_cur, UU, n0, 0, FF);
    else
        gemmW<0,1>(g_As, FF * NBF, nullptr, spline_w, FF * NBF, g_cur, UU,
                   n0, (part - 1) * 128, 128);
}

/* 4 gate GEMMs, A = [cur/S | h_prev] built in A-load   grid (4, 4, 8) */
__global__ void k_lstm(const float* __restrict__ h_prev,
                       const float* __restrict__ wf, const float* __restrict__ wi,
                       const float* __restrict__ wc, const float* __restrict__ wo)
{
    const float* w = (blockIdx.y == 0) ? wf : (blockIdx.y == 1) ? wi
                   : (blockIdx.y == 2) ? wc : wo;
    float* o = g_gates + (size_t)blockIdx.y * BU;
    gemmW<3,0>(g_cur, UU, h_prev, w, UU, o, UU,
               blockIdx.x * 128, blockIdx.z * 128, 128);
}

/* gate nonlinearities + state update */
__global__ void k_fin(const float* __restrict__ c_prev,
                      const float* __restrict__ bf, const float* __restrict__ bi,
                      const float* __restrict__ bc, const float* __restrict__ bo,
                      float* __restrict__ out, int out_size)
{
    int i = blockIdx.x * blockDim.x + threadIdx.x;
    int u = i & (UU - 1);
    float fg = 1.f / (1.f + __expf(-(g_gates[i]          + bf[u])));
    float ig = 1.f / (1.f + __expf(-(g_gates[BU + i]     + bi[u])));
    float cd = tanhf(              g_gates[2 * BU + i]   + bc[u]);
    float og = 1.f / (1.f + __expf(-(g_gates[3 * BU + i] + bo[u])));
    float c = fg * c_prev[i] + ig * cd;
    float h = og * tanhf(c);
    out[i] = h;
    if (out_size >= 2 * BU) out[BU + i] = c;
}

/* ------------------------------------------------------------------ */
extern "C" void kernel_launch(void* const* d_in, const int* in_sizes, int n_in,
                              void* d_out, int out_size)
{
    const float* X       = (const float*)d_in[0];
    const float* h_prev  = (const float*)d_in[1];
    const float* c_prev  = (const float*)d_in[2];
    const float* tk      = (const float*)d_in[3];
    const float* base_w  = (const float*)d_in[4];
    const float* spl_w   = (const float*)d_in[5];
    const float* w1      = (const float*)d_in[6];
    const float* b1      = (const float*)d_in[7];
    const float* w2      = (const float*)d_in[8];
    const float* b2      = (const float*)d_in[9];
    const float* w3      = (const float*)d_in[10];
    const float* b3      = (const float*)d_in[11];
    const float* w4      = (const float*)d_in[12];
    const float* b4      = (const float*)d_in[13];
    const float* ws      = (const float*)d_in[14];
    const float* bs      = (const float*)d_in[15];
    const float* gamma   = (const float*)d_in[16];
    const float* beta    = (const float*)d_in[17];
    const float* wf      = (const float*)d_in[18];
    const float* bf      = (const float*)d_in[19];
    const float* wi      = (const float*)d_in[20];
    const float* bi      = (const float*)d_in[21];
    const float* wc      = (const float*)d_in[22];
    const float* bc      = (const float*)d_in[23];
    const float* wo      = (const float*)d_in[24];
    const float* bo      = (const float*)d_in[25];
    float* out = (float*)d_out;

    k_zero   <<<256, 256>>>();
    k_sig    <<<dim3(2, BB), 256>>>(X, tk);
    k_siggemm<<<dim3(4, 43, 2), 256>>>(w1, ws);
    k_h2     <<<dim3(4, 16), 256>>>(b1, w2);
    k_g34    <<<dim3(4, 8, 2), 256>>>(b2, w3, w4);
    k_lnsm   <<<BB, 512>>>(b3, b4, bs, gamma, beta);
    k_reduce <<<dim3(BB, 8), 128>>>(X, tk);
    k_cur    <<<dim3(4, 9), 256>>>(base_w, spl_w);
    k_lstm   <<<dim3(4, 4, 8), 256>>>(h_prev, wf, wi, wc, wo);
    k_fin    <<<BU / 256, 256>>>(c_prev, bf, bi, bc, bo, out, out_size);
}